// round 10
// baseline (speedup 1.0000x reference)
#include <cuda_runtime.h>
#include <cuda_bf16.h>
#include <mma.h>
#include <cstddef>

using namespace nvcuda;

#define BATCH 256
#define HID   512
#define NBLK  128           // 8 row-groups x 16 col-tiles, all co-resident
#define WPAD  40            // W smem row stride (elems): 80B rows, LDSM conflict-free
#define KC2   256           // K-chunk (elems) per pipeline stage
#define APAD2 264           // A chunk row stride: 528B rows (33*16B), LDSM conflict-free
#define RPAD  36            // reduction row stride (fp32)

// ---- scratch (static __device__, allocation-free per harness rules) ----
__device__ __nv_bfloat16 g_Ehi[32000 * HID];     // pre-split embedding, hi plane
__device__ __nv_bfloat16 g_Elo[32000 * HID];     // lo plane
__device__ __nv_bfloat16 g_Hhi[2][BATCH * HID];  // ping-pong hidden state, hi
__device__ __nv_bfloat16 g_Hlo[2][BATCH * HID];  // lo
__device__ unsigned      g_bar[8 * 32];          // per-row-group barrier counters

struct ABuf { __nv_bfloat16 hi[32][APAD2]; __nv_bfloat16 lo[32][APAD2]; }; // 33792B

struct SMem {
    __nv_bfloat16 Whi[1024][WPAD];     // 81920B  block's W col slice, hi plane
    __nv_bfloat16 Wlo[1024][WPAD];     // 81920B  lo plane
    union {
        ABuf  buf[2];                  // 67584B  double-buffered A chunks
        float red[8][32][RPAD];        // 36864B  warp-partial reduction
    } u;
    int stok[32];
};                                      // ~231.6KB total

// tokens may be int32 (jax default) or int64. tokens[0][1] is a real token
// >= 3, so a zero second 32-bit word means little-endian int64.
__device__ __forceinline__ int load_tok(const int* tokens, long long idx)
{
    if (tokens[1] == 0) return (int)((const long long*)tokens)[idx];
    return tokens[idx];
}

__device__ __forceinline__ void split_bf16(float x, __nv_bfloat16& hi, __nv_bfloat16& lo)
{
    hi = __float2bfloat16(x);
    lo = __float2bfloat16(x - __bfloat162float(hi));
}

__device__ __forceinline__ void cp_async16(void* dst, const void* src)
{
    unsigned d = (unsigned)__cvta_generic_to_shared(dst);
    asm volatile("cp.async.cg.shared.global [%0], [%1], 16;" :: "r"(d), "l"(src));
}
__device__ __forceinline__ void cp_commit()
{
    asm volatile("cp.async.commit_group;" ::: "memory");
}
template <int N> __device__ __forceinline__ void cp_wait()
{
    asm volatile("cp.async.wait_group %0;" :: "n"(N) : "memory");
}

__device__ __forceinline__ void bar_arrive(unsigned* p)
{
    asm volatile("red.release.gpu.global.add.u32 [%0], %1;"
                 :: "l"(p), "r"(1u) : "memory");
}
__device__ __forceinline__ unsigned bar_peek(const unsigned* p)
{
    unsigned v;
    asm volatile("ld.acquire.gpu.global.u32 %0, [%1];"
                 : "=r"(v) : "l"(p) : "memory");
    return v;
}

// ---- pre-split the embedding table into bf16 hi/lo planes ----
__global__ void prep_emb(const float* __restrict__ emb, int n)
{
    int e = (blockIdx.x * blockDim.x + threadIdx.x) * 4;
    if (e >= n) return;
    float4 v = __ldcs((const float4*)(emb + e));
    float xs[4] = {v.x, v.y, v.z, v.w};
    __nv_bfloat16 h[4], l[4];
    #pragma unroll
    for (int j = 0; j < 4; ++j) split_bf16(xs[j], h[j], l[j]);
    __nv_bfloat162 h01 = __halves2bfloat162(h[0], h[1]);
    __nv_bfloat162 h23 = __halves2bfloat162(h[2], h[3]);
    __nv_bfloat162 l01 = __halves2bfloat162(l[0], l[1]);
    __nv_bfloat162 l23 = __halves2bfloat162(l[2], l[3]);
    __stcs((uint2*)&g_Ehi[e], make_uint2(*(unsigned*)&h01, *(unsigned*)&h23));
    __stcs((uint2*)&g_Elo[e], make_uint2(*(unsigned*)&l01, *(unsigned*)&l23));
}

// ---- h0 = emb[tok0] (already split) ; reset barrier counters ----
__global__ void init_kernel(const int* __restrict__ tokens)
{
    if (blockIdx.x == 0 && threadIdx.x < 8) g_bar[threadIdx.x * 32] = 0u;
    int b = blockIdx.x;
    long long tok = load_tok(tokens, b);
    int c = threadIdx.x * 4;                    // 128 threads x 4 cols
    *(uint2*)&g_Hhi[0][(size_t)b * HID + c] = *(const uint2*)&g_Ehi[tok * HID + c];
    *(uint2*)&g_Hlo[0][(size_t)b * HID + c] = *(const uint2*)&g_Elo[tok * HID + c];
}

// issue cp.async for one 32x256 hi/lo A chunk (c: 0,1 = E halves; 2,3 = H halves)
__device__ __forceinline__ void issue_chunk(SMem& sm, int c, int s, int rb)
{
    const int b   = c & 1;
    const int t   = threadIdx.x;
    const int row = t >> 3;
    const int seg = (t & 7) * 32;
    const __nv_bfloat16 *sh, *sl;
    if (c < 2) {
        size_t o = (size_t)sm.stok[row] * HID + c * KC2 + seg;
        sh = g_Ehi + o;  sl = g_Elo + o;
    } else {
        size_t o = (size_t)(rb + row) * HID + (c - 2) * KC2 + seg;
        sh = g_Hhi[(s - 1) & 1] + o;  sl = g_Hlo[(s - 1) & 1] + o;
    }
    __nv_bfloat16* dh = &sm.u.buf[b].hi[row][seg];
    __nv_bfloat16* dl = &sm.u.buf[b].lo[row][seg];
    #pragma unroll
    for (int i = 0; i < 4; ++i) {
        cp_async16(dh + i * 8, sh + i * 8);
        cp_async16(dl + i * 8, sl + i * 8);
    }
    cp_commit();
}

// Persistent chain kernel: 255 reduce steps, one launch.
// Block = 32x32 output tile; 8 warps split the fused K=1024 = [H | E].
// Per step: 4 pipelined chunks (E0,E1,H0,H1) of K=256 through 2 smem buffers;
// E chunks of step s+1 are issued at the end of step s so their DRAM latency
// hides inside the inter-block barrier. 3-term bf16-split wmma per chunk.
__global__ void __launch_bounds__(256, 1)
chain_kernel(const int* __restrict__ tokens,
             const float* __restrict__ Wl,
             const float* __restrict__ Wr,
             const float* __restrict__ bias,
             float* __restrict__ out,
             int nsteps)
{
    extern __shared__ char smem_raw[];
    SMem& sm = *reinterpret_cast<SMem*>(smem_raw);

    const int tid = threadIdx.x;
    const int w   = tid >> 5;
    const int rg  = blockIdx.x >> 4;       // row group 0..7 (independent chains)
    const int rb  = rg * 32;
    const int cb  = (blockIdx.x & 15) * 32;
    unsigned* barp = &g_bar[rg * 32];

    // ---- one-time: load + split this block's W column slice into smem ----
    {
        const int row0 = tid >> 3;
        const int cq   = (tid & 7) * 4;
        for (int it = 0; it < 32; ++it) {
            int row = it * 32 + row0;                  // 0..1023 over [Wl ; Wr]
            const float* src = (row < HID)
                ? (Wl + (size_t)row * HID + cb + cq)
                : (Wr + (size_t)(row - HID) * HID + cb + cq);
            float4 v = *(const float4*)src;
            float xs[4] = {v.x, v.y, v.z, v.w};
            #pragma unroll
            for (int j = 0; j < 4; ++j) {
                __nv_bfloat16 h, l;
                split_bf16(xs[j], h, l);
                sm.Whi[row][cq + j] = h;
                sm.Wlo[row][cq + j] = l;
            }
        }
    }

    // epilogue role + cached bias
    const int er  = tid >> 3;
    const int ec0 = (tid & 7) * 4;
    const float4 bias4 = *(const float4*)(bias + cb + ec0);

    // prologue: tokens for step 1, then issue E0,E1 of step 1
    if (tid < 32) sm.stok[tid] = load_tok(tokens, (long long)1 * BATCH + rb + tid);
    __syncthreads();
    issue_chunk(sm, 0, 1, rb);
    issue_chunk(sm, 1, 1, rb);

    for (int s = 1; s <= nsteps; ++s) {
        // prefetch next step's tokens into a register (off critical path)
        int treg = 0;
        if (tid < 32 && s < nsteps)
            treg = load_tok(tokens, (long long)(2 * s + 1) * BATCH + rb + tid);

        wmma::fragment<wmma::accumulator, 16, 16, 16, float> acc[2][2];
        #pragma unroll
        for (int mi = 0; mi < 2; ++mi)
            #pragma unroll
            for (int ni = 0; ni < 2; ++ni)
                wmma::fill_fragment(acc[mi][ni], 0.0f);

        #pragma unroll
        for (int c = 0; c < 4; ++c) {
            // wait for chunk c (allow the one newer chunk to keep flying)
            if (c < 3) cp_wait<1>(); else cp_wait<0>();
            __syncthreads();

            // compute chunk c: warp w owns k-cols [w*32, w*32+32) of the chunk
            {
                const int b  = c & 1;
                const int ak = w * 32;
                const int wb = (c < 2 ? 512 + c * KC2 : (c - 2) * KC2) + w * 32;
                #pragma unroll
                for (int kk = 0; kk < 2; ++kk) {
                    wmma::fragment<wmma::matrix_a, 16, 16, 16, __nv_bfloat16, wmma::row_major> ah[2], al[2];
                    wmma::fragment<wmma::matrix_b, 16, 16, 16, __nv_bfloat16, wmma::row_major> bh[2], bl[2];
                    #pragma unroll
                    for (int mi = 0; mi < 2; ++mi) {
                        wmma::load_matrix_sync(ah[mi], &sm.u.buf[b].hi[mi * 16][ak + kk * 16], APAD2);
                        wmma::load_matrix_sync(al[mi], &sm.u.buf[b].lo[mi * 16][ak + kk * 16], APAD2);
                    }
                    #pragma unroll
                    for (int ni = 0; ni < 2; ++ni) {
                        wmma::load_matrix_sync(bh[ni], &sm.Whi[wb + kk * 16][ni * 16], WPAD);
                        wmma::load_matrix_sync(bl[ni], &sm.Wlo[wb + kk * 16][ni * 16], WPAD);
                    }
                    #pragma unroll
                    for (int mi = 0; mi < 2; ++mi)
                        #pragma unroll
                        for (int ni = 0; ni < 2; ++ni) {
                            wmma::mma_sync(acc[mi][ni], ah[mi], bh[ni], acc[mi][ni]);
                            wmma::mma_sync(acc[mi][ni], ah[mi], bl[ni], acc[mi][ni]);
                            wmma::mma_sync(acc[mi][ni], al[mi], bh[ni], acc[mi][ni]);
                        }
                }
            }
            __syncthreads();           // buffer free for the next issue

            if (c == 0) {
                // barrier: peers' step s-1 H writes must be visible before H staging
                if (s > 1) {
                    if (tid == 0) {
                        const unsigned target = 16u * (unsigned)(s - 1);
                        while (bar_peek(barp) < target) { }
                    }
                    __syncthreads();
                }
                issue_chunk(sm, 2, s, rb);     // H first half
            } else if (c == 1) {
                issue_chunk(sm, 3, s, rb);     // H second half
            }
        }

        // ---- reduce 8 warp partials (A buffers dead; union reuse) ----
        #pragma unroll
        for (int mi = 0; mi < 2; ++mi)
            #pragma unroll
            for (int ni = 0; ni < 2; ++ni)
                wmma::store_matrix_sync(&sm.u.red[w][mi * 16][ni * 16],
                                        acc[mi][ni], RPAD, wmma::mem_row_major);
        __syncthreads();

        // ---- epilogue: bias + tanh; write bf16 hi/lo planes (or fp32 out) ----
        {
            float4 sum = *(const float4*)&sm.u.red[0][er][ec0];
            #pragma unroll
            for (int p = 1; p < 8; ++p) {
                float4 t = *(const float4*)&sm.u.red[p][er][ec0];
                sum.x += t.x; sum.y += t.y; sum.z += t.z; sum.w += t.w;
            }
            float v0 = tanhf(sum.x + bias4.x);
            float v1 = tanhf(sum.y + bias4.y);
            float v2 = tanhf(sum.z + bias4.z);
            float v3 = tanhf(sum.w + bias4.w);

            size_t o = (size_t)(rb + er) * HID + cb + ec0;
            if (s == nsteps) {
                *(float4*)&out[o] = make_float4(v0, v1, v2, v3);
            } else {
                __nv_bfloat16 h0, l0, h1, l1, h2, l2, h3, l3;
                split_bf16(v0, h0, l0);
                split_bf16(v1, h1, l1);
                split_bf16(v2, h2, l2);
                split_bf16(v3, h3, l3);
                __nv_bfloat162 hi01 = __halves2bfloat162(h0, h1);
                __nv_bfloat162 hi23 = __halves2bfloat162(h2, h3);
                __nv_bfloat162 lo01 = __halves2bfloat162(l0, l1);
                __nv_bfloat162 lo23 = __halves2bfloat162(l2, l3);
                *(uint2*)&g_Hhi[s & 1][o] =
                    make_uint2(*(unsigned*)&hi01, *(unsigned*)&hi23);
                *(uint2*)&g_Hlo[s & 1][o] =
                    make_uint2(*(unsigned*)&lo01, *(unsigned*)&lo23);
            }
        }

        if (s < nsteps) {
            // publish next step's tokens (E issue below reads sm.stok)
            if (tid < 32) sm.stok[tid] = treg;
            __syncthreads();                 // epilogue red reads done; stok visible

            if (tid == 0) bar_arrive(barp);  // release: our H writes visible
            issue_chunk(sm, 0, s + 1, rb);   // next step's E copies fly through
            issue_chunk(sm, 1, s + 1, rb);   // the barrier wait
        }
    }
}

extern "C" void kernel_launch(void* const* d_in, const int* in_sizes, int n_in,
                              void* d_out, int out_size)
{
    const int*   tokens = (const int*)  d_in[0];   // [511, 256]
    const float* emb    = (const float*)d_in[1];   // [32000, 512]
    const float* Wl     = (const float*)d_in[2];   // [512, 512]
    const float* Wr     = (const float*)d_in[3];   // [512, 512]
    const float* bias   = (const float*)d_in[4];   // [512]
    float* out = (float*)d_out;                    // [256, 512]

    const int T      = in_sizes[0] / BATCH;  // 511
    const int nsteps = (T - 1) / 2;          // 255 reduce steps
    const int nemb   = in_sizes[1];          // 32000*512

    cudaFuncSetAttribute(chain_kernel,
                         cudaFuncAttributeMaxDynamicSharedMemorySize,
                         (int)sizeof(SMem));

    prep_emb<<<(nemb / 4 + 255) / 256, 256>>>(emb, nemb);
    init_kernel<<<BATCH, HID / 4>>>(tokens);
    chain_kernel<<<NBLK, 256, sizeof(SMem)>>>(tokens, Wl, Wr, bias, out, nsteps);
}

// round 11
// speedup vs baseline: 1.9385x; 1.9385x over previous
#include <cuda_runtime.h>
#include <cuda_fp16.h>
#include <mma.h>
#include <cstddef>

using namespace nvcuda;

#define BATCH 256
#define HID   512
#define NBLK  128           // 8 row-groups x 16 col-tiles, all co-resident
#define WKS   1032          // W k-major stride (elems): 2064B rows, LDSM conflict-free
#define AS    520           // A row stride (elems): 1040B rows, LDSM conflict-free
#define RPAD  36            // reduction row stride (fp32), float4-aligned

// ---- scratch (static __device__, allocation-free per harness rules) ----
__device__ __half    g_E[32000 * HID];      // embedding, fp16 (unsplit)
__device__ __half    g_Hh[2][BATCH * HID];  // ping-pong hidden state, fp16 hi
__device__ __half    g_Hl[2][BATCH * HID];  // fp16 residual
__device__ unsigned  g_bar[8 * 32];         // per-row-group barrier counters

struct SMem {
    __half Wth[32][WKS];                 // 66048B  W col-slice, k-major, hi
    __half Wtl[32][WKS];                 // 66048B  lo
    __half E[32][AS];                    // 33280B  persistent E buffer
    union {
        __half Hp[2][32][AS];            // 66560B  H hi/lo staging
        float  red[8][32][RPAD];         // 36864B  warp-partial reduction
    } u;
    int stok[32];
};                                        // 232064B total (<= 232448 limit)

// tokens may be int32 (jax default) or int64. tokens[0][1] is a real token
// >= 3, so a zero second 32-bit word means little-endian int64.
__device__ __forceinline__ int load_tok(const int* tokens, long long idx)
{
    if (tokens[1] == 0) return (int)((const long long*)tokens)[idx];
    return tokens[idx];
}

__device__ __forceinline__ void split_h(float x, __half& hi, __half& lo)
{
    hi = __float2half_rn(x);
    lo = __float2half_rn(x - __half2float(hi));
}

__device__ __forceinline__ void cp_async16(void* dst, const void* src)
{
    unsigned d = (unsigned)__cvta_generic_to_shared(dst);
    asm volatile("cp.async.cg.shared.global [%0], [%1], 16;" :: "r"(d), "l"(src));
}
__device__ __forceinline__ void cp_commit()
{
    asm volatile("cp.async.commit_group;" ::: "memory");
}
template <int N> __device__ __forceinline__ void cp_wait()
{
    asm volatile("cp.async.wait_group %0;" :: "n"(N) : "memory");
}

__device__ __forceinline__ void bar_arrive(unsigned* p)
{
    asm volatile("red.release.gpu.global.add.u32 [%0], %1;"
                 :: "l"(p), "r"(1u) : "memory");
}
__device__ __forceinline__ unsigned bar_peek(const unsigned* p)
{
    unsigned v;
    asm volatile("ld.acquire.gpu.global.u32 %0, [%1];"
                 : "=r"(v) : "l"(p) : "memory");
    return v;
}

// ---- convert the embedding table to fp16 (single plane) ----
__global__ void prep_emb(const float* __restrict__ emb, int n)
{
    int e = (blockIdx.x * blockDim.x + threadIdx.x) * 4;
    if (e >= n) return;
    float4 v = __ldcs((const float4*)(emb + e));
    __half2 p01 = __floats2half2_rn(v.x, v.y);
    __half2 p23 = __floats2half2_rn(v.z, v.w);
    __stcs((uint2*)&g_E[e], make_uint2(*(unsigned*)&p01, *(unsigned*)&p23));
}

// ---- h0 = emb[tok0] split to fp16 hi/lo ; reset barrier counters ----
__global__ void init_kernel(const int* __restrict__ tokens,
                            const float* __restrict__ emb)
{
    if (blockIdx.x == 0 && threadIdx.x < 8) g_bar[threadIdx.x * 32] = 0u;
    int b = blockIdx.x;
    long long tok = load_tok(tokens, b);
    int c = threadIdx.x * 4;                    // 128 threads x 4 cols
    float4 v = *(const float4*)(emb + tok * HID + c);
    __half h[4], l[4];
    split_h(v.x, h[0], l[0]); split_h(v.y, h[1], l[1]);
    split_h(v.z, h[2], l[2]); split_h(v.w, h[3], l[3]);
    __half2 hh01 = __halves2half2(h[0], h[1]), hh23 = __halves2half2(h[2], h[3]);
    __half2 ll01 = __halves2half2(l[0], l[1]), ll23 = __halves2half2(l[2], l[3]);
    size_t o = (size_t)b * HID + c;
    *(uint2*)&g_Hh[0][o] = make_uint2(*(unsigned*)&hh01, *(unsigned*)&hh23);
    *(uint2*)&g_Hl[0][o] = make_uint2(*(unsigned*)&ll01, *(unsigned*)&ll23);
}

// issue cp.async: whole E tile (32 rows x 512) into the persistent E buffer
__device__ __forceinline__ void issue_E(SMem& sm)
{
    const int t   = threadIdx.x;
    const int row = t >> 3;
    const int seg = (t & 7) * 64;
    const __half* src = g_E + (size_t)sm.stok[row] * HID + seg;
    __half* dst = &sm.E[row][seg];
    #pragma unroll
    for (int i = 0; i < 8; ++i) cp_async16(dst + i * 8, src + i * 8);
    cp_commit();
}

// issue cp.async: H chunk c (k in [c*256, c*256+256)), hi+lo planes
__device__ __forceinline__ void issue_H(SMem& sm, int c, int s, int rb)
{
    const int t   = threadIdx.x;
    const int row = t >> 3;
    const int kb  = c * 256 + (t & 7) * 32;
    size_t o = (size_t)(rb + row) * HID + kb;
    const __half* sh = g_Hh[(s - 1) & 1] + o;
    const __half* sl = g_Hl[(s - 1) & 1] + o;
    #pragma unroll
    for (int i = 0; i < 4; ++i) {
        cp_async16(&sm.u.Hp[0][row][kb + i * 8], sh + i * 8);
        cp_async16(&sm.u.Hp[1][row][kb + i * 8], sl + i * 8);
    }
    cp_commit();
}

// Persistent chain kernel: 255 reduce steps, one launch.
// Block = 32x32 output tile; 8 warps split K. Per step:
//   E phase: K=512, E unsplit fp16, W split -> 2 terms (Eh*Wh + Eh*Wl)
//   H phase: K=512, H split fp16 hi/lo   -> 3 terms (HhWh + HhWl + HlWh)
// W slice (k-major, fp16 hi/lo) resident in smem for the whole kernel.
// Next step's E tile is prefetched before the inter-block barrier so its
// DRAM latency hides inside the barrier wait; H is 2-chunked over L2.
__global__ void __launch_bounds__(256, 1)
chain_kernel(const int* __restrict__ tokens,
             const float* __restrict__ Wl,
             const float* __restrict__ Wr,
             const float* __restrict__ bias,
             float* __restrict__ out,
             int nsteps)
{
    extern __shared__ char smem_raw[];
    SMem& sm = *reinterpret_cast<SMem*>(smem_raw);

    const int tid = threadIdx.x;
    const int w   = tid >> 5;
    const int rg  = blockIdx.x >> 4;        // row group 0..7 (independent chains)
    const int rb  = rg * 32;
    const int cb  = (blockIdx.x & 15) * 32;
    unsigned* barp = &g_bar[rg * 32];

    // ---- one-time: load + split W col slice into k-major smem planes ----
    {
        const int col = tid & 31;
        const int kr  = tid >> 5;            // 8 k-rows per iter
        for (int it = 0; it < 128; ++it) {
            int k = it * 8 + kr;             // 0..1023 over [Wl ; Wr]
            float v = (k < HID) ? Wl[(size_t)k * HID + cb + col]
                                : Wr[(size_t)(k - HID) * HID + cb + col];
            __half h, l;
            split_h(v, h, l);
            sm.Wth[col][k] = h;
            sm.Wtl[col][k] = l;
        }
    }

    // epilogue role + cached bias
    const int er  = tid >> 3;
    const int ec0 = (tid & 7) * 4;
    const float4 bias4 = *(const float4*)(bias + cb + ec0);

    // prologue: step-1 tokens, then prefetch step-1 E
    if (tid < 32) sm.stok[tid] = load_tok(tokens, (long long)BATCH + rb + tid);
    __syncthreads();
    issue_E(sm);

    for (int s = 1; s <= nsteps; ++s) {
        // prefetch next step's tokens (off critical path; tokens L1-resident)
        int treg = 0;
        if (tid < 32 && s < nsteps)
            treg = load_tok(tokens, (long long)(2 * s + 1) * BATCH + rb + tid);

        wmma::fragment<wmma::accumulator, 16, 16, 16, float> acc[2][2];
        #pragma unroll
        for (int mi = 0; mi < 2; ++mi)
            #pragma unroll
            for (int ni = 0; ni < 2; ++ni)
                wmma::fill_fragment(acc[mi][ni], 0.0f);

        // ---- E phase: K=512, 2 terms, warp owns 64 k-cols ----
        cp_wait<0>();
        __syncthreads();
        #pragma unroll
        for (int kk = 0; kk < 4; ++kk) {
            const int kl = w * 64 + kk * 16;       // within E's K
            const int kf = HID + kl;               // fused k (Wr half)
            wmma::fragment<wmma::matrix_a, 16, 16, 16, __half, wmma::row_major> ah[2];
            wmma::fragment<wmma::matrix_b, 16, 16, 16, __half, wmma::col_major> bh[2], bl[2];
            #pragma unroll
            for (int mi = 0; mi < 2; ++mi)
                wmma::load_matrix_sync(ah[mi], &sm.E[mi * 16][kl], AS);
            #pragma unroll
            for (int ni = 0; ni < 2; ++ni) {
                wmma::load_matrix_sync(bh[ni], &sm.Wth[ni * 16][kf], WKS);
                wmma::load_matrix_sync(bl[ni], &sm.Wtl[ni * 16][kf], WKS);
            }
            #pragma unroll
            for (int mi = 0; mi < 2; ++mi)
                #pragma unroll
                for (int ni = 0; ni < 2; ++ni) {
                    wmma::mma_sync(acc[mi][ni], ah[mi], bh[ni], acc[mi][ni]);
                    wmma::mma_sync(acc[mi][ni], ah[mi], bl[ni], acc[mi][ni]);
                }
        }

        // ---- barrier: peers' step s-1 H writes must be visible ----
        if (s > 1) {
            if (tid == 0) {
                const unsigned target = 16u * (unsigned)(s - 1);
                while (bar_peek(barp) < target) { }
            }
        }
        __syncthreads();

        issue_H(sm, 0, s, rb);
        issue_H(sm, 1, s, rb);

        // ---- H phase: K=512, 3 terms, 2 chunks, warp owns 32 k-cols/chunk ----
        #pragma unroll
        for (int c = 0; c < 2; ++c) {
            if (c == 0) cp_wait<1>(); else cp_wait<0>();
            __syncthreads();
            #pragma unroll
            for (int kk = 0; kk < 2; ++kk) {
                const int kl = c * 256 + w * 32 + kk * 16;  // fused k (Wl half)
                wmma::fragment<wmma::matrix_a, 16, 16, 16, __half, wmma::row_major> ah[2], al[2];
                wmma::fragment<wmma::matrix_b, 16, 16, 16, __half, wmma::col_major> bh[2], bl[2];
                #pragma unroll
                for (int mi = 0; mi < 2; ++mi) {
                    wmma::load_matrix_sync(ah[mi], &sm.u.Hp[0][mi * 16][kl], AS);
                    wmma::load_matrix_sync(al[mi], &sm.u.Hp[1][mi * 16][kl], AS);
                }
                #pragma unroll
                for (int ni = 0; ni < 2; ++ni) {
                    wmma::load_matrix_sync(bh[ni], &sm.Wth[ni * 16][kl], WKS);
                    wmma::load_matrix_sync(bl[ni], &sm.Wtl[ni * 16][kl], WKS);
                }
                #pragma unroll
                for (int mi = 0; mi < 2; ++mi)
                    #pragma unroll
                    for (int ni = 0; ni < 2; ++ni) {
                        wmma::mma_sync(acc[mi][ni], ah[mi], bh[ni], acc[mi][ni]);
                        wmma::mma_sync(acc[mi][ni], ah[mi], bl[ni], acc[mi][ni]);
                        wmma::mma_sync(acc[mi][ni], al[mi], bh[ni], acc[mi][ni]);
                    }
            }
        }
        __syncthreads();                     // H reads done; red overlays Hp

        // ---- reduce 8 warp partials ----
        #pragma unroll
        for (int mi = 0; mi < 2; ++mi)
            #pragma unroll
            for (int ni = 0; ni < 2; ++ni)
                wmma::store_matrix_sync(&sm.u.red[w][mi * 16][ni * 16],
                                        acc[mi][ni], RPAD, wmma::mem_row_major);
        __syncthreads();

        // ---- epilogue: bias + tanh; write fp16 hi/lo planes (or fp32 out) ----
        {
            float4 sum = *(const float4*)&sm.u.red[0][er][ec0];
            #pragma unroll
            for (int p = 1; p < 8; ++p) {
                float4 t = *(const float4*)&sm.u.red[p][er][ec0];
                sum.x += t.x; sum.y += t.y; sum.z += t.z; sum.w += t.w;
            }
            float v0 = tanhf(sum.x + bias4.x);
            float v1 = tanhf(sum.y + bias4.y);
            float v2 = tanhf(sum.z + bias4.z);
            float v3 = tanhf(sum.w + bias4.w);

            size_t o = (size_t)(rb + er) * HID + cb + ec0;
            if (s == nsteps) {
                *(float4*)&out[o] = make_float4(v0, v1, v2, v3);
            } else {
                __half h0, l0, h1, l1, h2, l2, h3, l3;
                split_h(v0, h0, l0); split_h(v1, h1, l1);
                split_h(v2, h2, l2); split_h(v3, h3, l3);
                __half2 hh01 = __halves2half2(h0, h1), hh23 = __halves2half2(h2, h3);
                __half2 ll01 = __halves2half2(l0, l1), ll23 = __halves2half2(l2, l3);
                *(uint2*)&g_Hh[s & 1][o] =
                    make_uint2(*(unsigned*)&hh01, *(unsigned*)&hh23);
                *(uint2*)&g_Hl[s & 1][o] =
                    make_uint2(*(unsigned*)&ll01, *(unsigned*)&ll23);
            }
        }

        if (s < nsteps) {
            if (tid < 32) sm.stok[tid] = treg;   // publish next step's tokens
            __syncthreads();                     // red reads done; stok visible
            if (tid == 0) bar_arrive(barp);      // release: our H writes visible
            issue_E(sm);                         // next E flies through barrier
        }
    }
}

extern "C" void kernel_launch(void* const* d_in, const int* in_sizes, int n_in,
                              void* d_out, int out_size)
{
    const int*   tokens = (const int*)  d_in[0];   // [511, 256]
    const float* emb    = (const float*)d_in[1];   // [32000, 512]
    const float* Wl     = (const float*)d_in[2];   // [512, 512]
    const float* Wr     = (const float*)d_in[3];   // [512, 512]
    const float* bias   = (const float*)d_in[4];   // [512]
    float* out = (float*)d_out;                    // [256, 512]

    const int T      = in_sizes[0] / BATCH;  // 511
    const int nsteps = (T - 1) / 2;          // 255 reduce steps
    const int nemb   = in_sizes[1];          // 32000*512

    cudaFuncSetAttribute(chain_kernel,
                         cudaFuncAttributeMaxDynamicSharedMemorySize,
                         (int)sizeof(SMem));

    prep_emb<<<(nemb / 4 + 255) / 256, 256>>>(emb, nemb);
    init_kernel<<<BATCH, HID / 4>>>(tokens, emb);
    chain_kernel<<<NBLK, 256, sizeof(SMem)>>>(tokens, Wl, Wr, bias, out, nsteps);
}